// round 1
// baseline (speedup 1.0000x reference)
#include <cuda_runtime.h>

#define B 8
#define T 1024
#define D 512
#define H 8
#define DK 64
#define BT (B*T)   // 8192

// Scratch (static device globals — no runtime allocation)
__device__ float g_q[BT * D];
__device__ float g_k[BT * D];
__device__ float g_v[BT * D];
__device__ float g_p[BT * D];
__device__ float g_cs[(size_t)B * H * T * T];   // content scores -> attn (in place)
__device__ float g_ps[(size_t)B * H * T * T];   // pos scores
__device__ float g_ctx[BT * D];

// ---------------------------------------------------------------------------
// C[M,N] = A[M,K] @ W[K,N] (+ bias[N]).  64x64 tile, 256 threads, 4x4 micro.
// M%64==0, N%64==0, K%16==0 assumed.
// ---------------------------------------------------------------------------
__global__ __launch_bounds__(256) void sgemm_bias(
    const float* __restrict__ A, const float* __restrict__ W,
    const float* __restrict__ bias, float* __restrict__ C,
    int M, int N, int K)
{
    __shared__ float As[16][65];   // [k][m] padded
    __shared__ float Bs[16][64];   // [k][n]
    int tid = threadIdx.x;
    int tx = tid & 15, ty = tid >> 4;
    int bm = blockIdx.y * 64, bn = blockIdx.x * 64;
    float acc[4][4] = {};

    for (int k0 = 0; k0 < K; k0 += 16) {
        #pragma unroll
        for (int l = 0; l < 4; l++) {
            int idx = tid + l * 256;             // 0..1023
            int m  = idx >> 4, kk  = idx & 15;   // A: 64 m x 16 k
            As[kk][m] = A[(size_t)(bm + m) * K + k0 + kk];
            int kk2 = idx >> 6, n  = idx & 63;   // B: 16 k x 64 n
            Bs[kk2][n] = W[(size_t)(k0 + kk2) * N + bn + n];
        }
        __syncthreads();
        #pragma unroll
        for (int kk = 0; kk < 16; kk++) {
            float a[4], b[4];
            #pragma unroll
            for (int r = 0; r < 4; r++) a[r] = As[kk][ty * 4 + r];
            #pragma unroll
            for (int c = 0; c < 4; c++) b[c] = Bs[kk][tx * 4 + c];
            #pragma unroll
            for (int r = 0; r < 4; r++)
                #pragma unroll
                for (int c = 0; c < 4; c++)
                    acc[r][c] = fmaf(a[r], b[c], acc[r][c]);
        }
        __syncthreads();
    }
    #pragma unroll
    for (int r = 0; r < 4; r++) {
        int m = bm + ty * 4 + r;
        #pragma unroll
        for (int c = 0; c < 4; c++) {
            int n = bn + tx * 4 + c;
            float v = acc[r][c];
            if (bias) v += bias[n];
            C[(size_t)m * N + n] = v;
        }
    }
}

// ---------------------------------------------------------------------------
// Scores: out[bh,i,j] = sum_d (q[b,i,h,d] + qbias[h,d]) * kp[b,j,h,d]
// grid (T/64, T/64, B*H); 64x64 tile, full K=64 in smem.
// ---------------------------------------------------------------------------
__global__ __launch_bounds__(256) void score_kernel(
    const float* __restrict__ q, const float* __restrict__ kp,
    const float* __restrict__ qbias, float* __restrict__ out)
{
    int bh = blockIdx.z;
    int b = bh >> 3, h = bh & 7;
    int bi = blockIdx.y * 64, bj = blockIdx.x * 64;
    __shared__ float Qs[64][65];
    __shared__ float Ks[64][65];
    int tid = threadIdx.x;
    int tx = tid & 15, ty = tid >> 4;

    #pragma unroll
    for (int l = 0; l < 16; l++) {
        int idx = l * 256 + tid;       // 0..4095
        int row = idx >> 6, d = idx & 63;
        Qs[row][d] = q[(size_t)((b * T + bi + row) * H + h) * DK + d] + qbias[h * DK + d];
        Ks[row][d] = kp[(size_t)((b * T + bj + row) * H + h) * DK + d];
    }
    __syncthreads();

    float acc[4][4] = {};
    #pragma unroll
    for (int d = 0; d < 64; d++) {
        float a[4], bb[4];
        #pragma unroll
        for (int r = 0; r < 4; r++) a[r] = Qs[ty * 4 + r][d];
        #pragma unroll
        for (int c = 0; c < 4; c++) bb[c] = Ks[tx * 4 + c][d];
        #pragma unroll
        for (int r = 0; r < 4; r++)
            #pragma unroll
            for (int c = 0; c < 4; c++)
                acc[r][c] = fmaf(a[r], bb[c], acc[r][c]);
    }

    size_t base = (size_t)bh * T * T;
    #pragma unroll
    for (int r = 0; r < 4; r++)
        #pragma unroll
        for (int c = 0; c < 4; c++)
            out[base + (size_t)(bi + ty * 4 + r) * T + bj + tx * 4 + c] = acc[r][c];
}

// ---------------------------------------------------------------------------
// Fused rel-shift + scale + softmax. One block per row (i', bh).
// shifted[i',j'] replicates the reference pad/reshape exactly:
//   flat=(i'+1)*T+j'; i=flat/(T+1); c=flat%(T+1); val = (c==0)?0:PS[i,c-1]
// In-place over cs is safe: each block reads/writes only its own cs row.
// ---------------------------------------------------------------------------
__global__ __launch_bounds__(256) void softmax_shift_kernel(
    const float* __restrict__ cs, const float* __restrict__ ps,
    float* __restrict__ attn)
{
    int i  = blockIdx.x;
    int bh = blockIdx.y;
    int tid = threadIdx.x;
    size_t base = (size_t)bh * T * T;
    const float inv = 0.04419417382415922f;   // 1/sqrt(512)

    float vals[4];
    float mx = -3.4e38f;
    #pragma unroll
    for (int l = 0; l < 4; l++) {
        int j = tid + l * 256;
        int flat = (i + 1) * T + j;
        int ii = flat / (T + 1);
        int c  = flat - ii * (T + 1);
        float pv = (c == 0) ? 0.0f : ps[base + (size_t)ii * T + (c - 1)];
        float s = (cs[base + (size_t)i * T + j] + pv) * inv;
        vals[l] = s;
        mx = fmaxf(mx, s);
    }

    __shared__ float red[8];
    #pragma unroll
    for (int o = 16; o > 0; o >>= 1) mx = fmaxf(mx, __shfl_xor_sync(0xffffffffu, mx, o));
    if ((tid & 31) == 0) red[tid >> 5] = mx;
    __syncthreads();
    if (tid == 0) {
        float m = red[0];
        #pragma unroll
        for (int w = 1; w < 8; w++) m = fmaxf(m, red[w]);
        red[0] = m;
    }
    __syncthreads();
    mx = red[0];
    __syncthreads();   // protect red[] before reuse

    float sum = 0.f;
    #pragma unroll
    for (int l = 0; l < 4; l++) { vals[l] = expf(vals[l] - mx); sum += vals[l]; }
    #pragma unroll
    for (int o = 16; o > 0; o >>= 1) sum += __shfl_xor_sync(0xffffffffu, sum, o);
    if ((tid & 31) == 0) red[tid >> 5] = sum;
    __syncthreads();
    if (tid == 0) {
        float s = 0.f;
        #pragma unroll
        for (int w = 0; w < 8; w++) s += red[w];
        red[0] = s;
    }
    __syncthreads();
    float rinv = 1.0f / red[0];
    #pragma unroll
    for (int l = 0; l < 4; l++) {
        int j = tid + l * 256;
        attn[base + (size_t)i * T + j] = vals[l] * rinv;
    }
}

// ---------------------------------------------------------------------------
// Context: ctx[b,i,h,d] = sum_j attn[bh,i,j] * v[b,j,h,d]
// grid (T/64, B*H). 64(i) x 64(d=DK) tile, K chunks of 32.
// ---------------------------------------------------------------------------
__global__ __launch_bounds__(256) void context_kernel(
    const float* __restrict__ attn, const float* __restrict__ v,
    float* __restrict__ ctx)
{
    int bh = blockIdx.y;
    int b = bh >> 3, h = bh & 7;
    int bi = blockIdx.x * 64;
    __shared__ float As[64][33];   // attn tile [i][j]
    __shared__ float Vs[32][64];   // v tile [j][d]
    int tid = threadIdx.x;
    int tx = tid & 15, ty = tid >> 4;
    float acc[4][4] = {};
    size_t abase = (size_t)bh * T * T;

    for (int k0 = 0; k0 < T; k0 += 32) {
        #pragma unroll
        for (int l = 0; l < 8; l++) {
            int idx = l * 256 + tid;           // 0..2047
            int row = idx >> 5, jj = idx & 31; // 64 x 32
            As[row][jj] = attn[abase + (size_t)(bi + row) * T + k0 + jj];
            int jr = idx >> 6, d = idx & 63;   // 32 x 64
            Vs[jr][d] = v[(size_t)((b * T + k0 + jr) * H + h) * DK + d];
        }
        __syncthreads();
        #pragma unroll
        for (int kk = 0; kk < 32; kk++) {
            float a[4], bb[4];
            #pragma unroll
            for (int r = 0; r < 4; r++) a[r] = As[ty * 4 + r][kk];
            #pragma unroll
            for (int c = 0; c < 4; c++) bb[c] = Vs[kk][tx * 4 + c];
            #pragma unroll
            for (int r = 0; r < 4; r++)
                #pragma unroll
                for (int c = 0; c < 4; c++)
                    acc[r][c] = fmaf(a[r], bb[c], acc[r][c]);
        }
        __syncthreads();
    }
    #pragma unroll
    for (int r = 0; r < 4; r++)
        #pragma unroll
        for (int c = 0; c < 4; c++)
            ctx[(size_t)((b * T + bi + ty * 4 + r) * H + h) * DK + tx * 4 + c] = acc[r][c];
}

// ---------------------------------------------------------------------------
extern "C" void kernel_launch(void* const* d_in, const int* in_sizes, int n_in,
                              void* d_out, int out_size)
{
    const float* query = (const float*)d_in[0];
    const float* key   = (const float*)d_in[1];
    const float* value = (const float*)d_in[2];
    const float* pos   = (const float*)d_in[3];
    const float* Wq = (const float*)d_in[4];
    const float* bq = (const float*)d_in[5];
    const float* Wk = (const float*)d_in[6];
    const float* bk = (const float*)d_in[7];
    const float* Wv = (const float*)d_in[8];
    const float* bv = (const float*)d_in[9];
    const float* Wp = (const float*)d_in[10];
    const float* ub = (const float*)d_in[11];
    const float* vb = (const float*)d_in[12];
    const float* Wo = (const float*)d_in[13];
    const float* bo = (const float*)d_in[14];
    float* out = (float*)d_out;

    float *q, *k, *v, *p, *cs, *ps, *ctx;
    cudaGetSymbolAddress((void**)&q,   g_q);
    cudaGetSymbolAddress((void**)&k,   g_k);
    cudaGetSymbolAddress((void**)&v,   g_v);
    cudaGetSymbolAddress((void**)&p,   g_p);
    cudaGetSymbolAddress((void**)&cs,  g_cs);
    cudaGetSymbolAddress((void**)&ps,  g_ps);
    cudaGetSymbolAddress((void**)&ctx, g_ctx);

    dim3 blk(256);
    dim3 gproj(D / 64, BT / 64);            // (8, 128)
    sgemm_bias<<<gproj, blk>>>(query, Wq, bq, q, BT, D, D);
    sgemm_bias<<<gproj, blk>>>(key,   Wk, bk, k, BT, D, D);
    sgemm_bias<<<gproj, blk>>>(value, Wv, bv, v, BT, D, D);
    sgemm_bias<<<gproj, blk>>>(pos,   Wp, nullptr, p, BT, D, D);

    dim3 gsc(T / 64, T / 64, B * H);        // (16, 16, 64)
    score_kernel<<<gsc, blk>>>(q, k, ub, cs);
    score_kernel<<<gsc, blk>>>(q, p, vb, ps);

    dim3 gsm(T, B * H);                     // (1024, 64)
    softmax_shift_kernel<<<gsm, blk>>>(cs, ps, cs);

    dim3 gctx(T / 64, B * H);               // (16, 64)
    context_kernel<<<gctx, blk>>>(cs, v, ctx);

    sgemm_bias<<<gproj, blk>>>(ctx, Wo, bo, out, BT, D, D);
}

// round 2
// speedup vs baseline: 1.2239x; 1.2239x over previous
#include <cuda_runtime.h>

#define B 8
#define T 1024
#define D 512
#define H 8
#define DK 64
#define BT (B*T)   // 8192

// Scratch (static device globals — no runtime allocation)
__device__ float g_q[BT * D];
__device__ float g_k[BT * D];
__device__ float g_v[BT * D];
__device__ float g_p[BT * D];
__device__ float g_cs[(size_t)B * H * T * T];   // content scores -> attn (in place)
__device__ float g_ps[(size_t)B * H * T * T];   // pos scores
__device__ float g_ctx[BT * D];

// ---------------------------------------------------------------------------
// TF32 helpers
// ---------------------------------------------------------------------------
__device__ __forceinline__ float f2tf32(float f) {
    unsigned u;
    asm("cvt.rna.tf32.f32 %0, %1;" : "=r"(u) : "f"(f));
    return __uint_as_float(u);
}

// mma.sync m16n8k8 tf32: D += A(16x8) * B(8x8)
// A frag (4 regs): a0=(g,t) a1=(g+8,t) a2=(g,t+4) a3=(g+8,t+4)
// B frag (2 regs): b0=(k=t,n=g) b1=(k=t+4,n=g)
// C frag (4 regs): c0=(g,2t) c1=(g,2t+1) c2=(g+8,2t) c3=(g+8,2t+1)
__device__ __forceinline__ void mma_tf32(float* c, const float* a, const float* b) {
    asm volatile(
        "mma.sync.aligned.m16n8k8.row.col.f32.tf32.tf32.f32 "
        "{%0,%1,%2,%3}, {%4,%5,%6,%7}, {%8,%9}, {%0,%1,%2,%3};"
        : "+f"(c[0]), "+f"(c[1]), "+f"(c[2]), "+f"(c[3])
        : "r"(__float_as_uint(a[0])), "r"(__float_as_uint(a[1])),
          "r"(__float_as_uint(a[2])), "r"(__float_as_uint(a[3])),
          "r"(__float_as_uint(b[0])), "r"(__float_as_uint(b[1])));
}

// ---------------------------------------------------------------------------
// GEMM (tensor core, tf32): C[M,N] = A[M,K] @ W[K,N] (+bias)
// Block tile 128x64, 256 threads (8 warps: 4m x 2n), warp tile 32x32, K step 32.
// M%128==0, N%64==0, K%32==0.
// ---------------------------------------------------------------------------
__global__ __launch_bounds__(256) void sgemm_bias_tc(
    const float* __restrict__ A, const float* __restrict__ W,
    const float* __restrict__ bias, float* __restrict__ C,
    int M, int N, int K)
{
    __shared__ float As[128][33];   // [m][k]
    __shared__ float Bs[32][65];    // [k][n]
    int tid = threadIdx.x;
    int warp = tid >> 5, lane = tid & 31;
    int gid = lane >> 2, tig = lane & 3;
    int wm = warp >> 1, wn = warp & 1;       // 4 x 2 warp grid
    int bm = blockIdx.y * 128, bn = blockIdx.x * 64;

    float acc[2][4][4] = {};

    for (int k0 = 0; k0 < K; k0 += 32) {
        // Load A tile: 128x32 = 1024 float4, 4 per thread
        #pragma unroll
        for (int l = 0; l < 4; l++) {
            int idx = tid + l * 256;
            int row = idx >> 3, c4 = (idx & 7) * 4;
            float4 v = *(const float4*)&A[(size_t)(bm + row) * K + k0 + c4];
            As[row][c4 + 0] = f2tf32(v.x);
            As[row][c4 + 1] = f2tf32(v.y);
            As[row][c4 + 2] = f2tf32(v.z);
            As[row][c4 + 3] = f2tf32(v.w);
        }
        // Load B tile: 32x64 = 512 float4, 2 per thread
        #pragma unroll
        for (int l = 0; l < 2; l++) {
            int idx = tid + l * 256;
            int row = idx >> 4, c4 = (idx & 15) * 4;
            float4 v = *(const float4*)&W[(size_t)(k0 + row) * N + bn + c4];
            Bs[row][c4 + 0] = f2tf32(v.x);
            Bs[row][c4 + 1] = f2tf32(v.y);
            Bs[row][c4 + 2] = f2tf32(v.z);
            Bs[row][c4 + 3] = f2tf32(v.w);
        }
        __syncthreads();

        #pragma unroll
        for (int k8 = 0; k8 < 4; k8++) {
            int kb = k8 * 8;
            float af[2][4], bf[4][2];
            #pragma unroll
            for (int mt = 0; mt < 2; mt++) {
                int r = wm * 32 + mt * 16 + gid;
                af[mt][0] = As[r][kb + tig];
                af[mt][1] = As[r + 8][kb + tig];
                af[mt][2] = As[r][kb + tig + 4];
                af[mt][3] = As[r + 8][kb + tig + 4];
            }
            #pragma unroll
            for (int nt = 0; nt < 4; nt++) {
                int cidx = wn * 32 + nt * 8 + gid;
                bf[nt][0] = Bs[kb + tig][cidx];
                bf[nt][1] = Bs[kb + tig + 4][cidx];
            }
            #pragma unroll
            for (int mt = 0; mt < 2; mt++)
                #pragma unroll
                for (int nt = 0; nt < 4; nt++)
                    mma_tf32(acc[mt][nt], af[mt], bf[nt]);
        }
        __syncthreads();
    }

    #pragma unroll
    for (int mt = 0; mt < 2; mt++) {
        int r0 = bm + wm * 32 + mt * 16 + gid;
        #pragma unroll
        for (int nt = 0; nt < 4; nt++) {
            int c0 = bn + wn * 32 + nt * 8 + 2 * tig;
            float b0 = bias ? bias[c0] : 0.f;
            float b1 = bias ? bias[c0 + 1] : 0.f;
            C[(size_t)r0 * N + c0]           = acc[mt][nt][0] + b0;
            C[(size_t)r0 * N + c0 + 1]       = acc[mt][nt][1] + b1;
            C[(size_t)(r0 + 8) * N + c0]     = acc[mt][nt][2] + b0;
            C[(size_t)(r0 + 8) * N + c0 + 1] = acc[mt][nt][3] + b1;
        }
    }
}

// ---------------------------------------------------------------------------
// Scores (tensor core): out[bh,i,j] = sum_d (q[b,i,h,d]+qbias[h,d]) * kp[b,j,h,d]
// Block tile 64i x 64j, 128 threads (4 warps: 2m x 2n), warp tile 32x32. K=64.
// ---------------------------------------------------------------------------
__global__ __launch_bounds__(128) void score_tc(
    const float* __restrict__ q, const float* __restrict__ kp,
    const float* __restrict__ qbias, float* __restrict__ out)
{
    __shared__ float Qs[64][65];   // [i][d]
    __shared__ float Ks[64][65];   // [j][d]
    int bh = blockIdx.z;
    int b = bh >> 3, h = bh & 7;
    int bi = blockIdx.y * 64, bj = blockIdx.x * 64;
    int tid = threadIdx.x;
    int warp = tid >> 5, lane = tid & 31;
    int gid = lane >> 2, tig = lane & 3;
    int wm = warp >> 1, wn = warp & 1;

    // Load Q tile (+bias) and K tile: each 64x64 = 1024 float4, 8 per thread
    #pragma unroll
    for (int l = 0; l < 8; l++) {
        int idx = tid + l * 128;
        int row = idx >> 4, c4 = (idx & 15) * 4;
        float4 vq = *(const float4*)&q[(size_t)((b * T + bi + row) * H + h) * DK + c4];
        float4 vb = *(const float4*)&qbias[h * DK + c4];
        Qs[row][c4 + 0] = f2tf32(vq.x + vb.x);
        Qs[row][c4 + 1] = f2tf32(vq.y + vb.y);
        Qs[row][c4 + 2] = f2tf32(vq.z + vb.z);
        Qs[row][c4 + 3] = f2tf32(vq.w + vb.w);
        float4 vk = *(const float4*)&kp[(size_t)((b * T + bj + row) * H + h) * DK + c4];
        Ks[row][c4 + 0] = f2tf32(vk.x);
        Ks[row][c4 + 1] = f2tf32(vk.y);
        Ks[row][c4 + 2] = f2tf32(vk.z);
        Ks[row][c4 + 3] = f2tf32(vk.w);
    }
    __syncthreads();

    float acc[2][4][4] = {};
    #pragma unroll
    for (int k8 = 0; k8 < 8; k8++) {
        int kb = k8 * 8;
        float af[2][4], bf[4][2];
        #pragma unroll
        for (int mt = 0; mt < 2; mt++) {
            int r = wm * 32 + mt * 16 + gid;
            af[mt][0] = Qs[r][kb + tig];
            af[mt][1] = Qs[r + 8][kb + tig];
            af[mt][2] = Qs[r][kb + tig + 4];
            af[mt][3] = Qs[r + 8][kb + tig + 4];
        }
        #pragma unroll
        for (int nt = 0; nt < 4; nt++) {
            int cidx = wn * 32 + nt * 8 + gid;
            bf[nt][0] = Ks[cidx][kb + tig];       // B[k=d][n=j] = Ks[j][d]
            bf[nt][1] = Ks[cidx][kb + tig + 4];
        }
        #pragma unroll
        for (int mt = 0; mt < 2; mt++)
            #pragma unroll
            for (int nt = 0; nt < 4; nt++)
                mma_tf32(acc[mt][nt], af[mt], bf[nt]);
    }

    size_t base = (size_t)bh * T * T;
    #pragma unroll
    for (int mt = 0; mt < 2; mt++) {
        int r0 = bi + wm * 32 + mt * 16 + gid;
        #pragma unroll
        for (int nt = 0; nt < 4; nt++) {
            int c0 = bj + wn * 32 + nt * 8 + 2 * tig;
            out[base + (size_t)r0 * T + c0]           = acc[mt][nt][0];
            out[base + (size_t)r0 * T + c0 + 1]       = acc[mt][nt][1];
            out[base + (size_t)(r0 + 8) * T + c0]     = acc[mt][nt][2];
            out[base + (size_t)(r0 + 8) * T + c0 + 1] = acc[mt][nt][3];
        }
    }
}

// ---------------------------------------------------------------------------
// Fused rel-shift + scale + softmax. One block per row (i, bh). Unchanged.
// ---------------------------------------------------------------------------
__global__ __launch_bounds__(256) void softmax_shift_kernel(
    const float* __restrict__ cs, const float* __restrict__ ps,
    float* __restrict__ attn)
{
    int i  = blockIdx.x;
    int bh = blockIdx.y;
    int tid = threadIdx.x;
    size_t base = (size_t)bh * T * T;
    const float inv = 0.04419417382415922f;   // 1/sqrt(512)

    float vals[4];
    float mx = -3.4e38f;
    #pragma unroll
    for (int l = 0; l < 4; l++) {
        int j = tid + l * 256;
        int flat = (i + 1) * T + j;
        int ii = flat / (T + 1);
        int c  = flat - ii * (T + 1);
        float pv = (c == 0) ? 0.0f : ps[base + (size_t)ii * T + (c - 1)];
        float s = (cs[base + (size_t)i * T + j] + pv) * inv;
        vals[l] = s;
        mx = fmaxf(mx, s);
    }

    __shared__ float red[8];
    #pragma unroll
    for (int o = 16; o > 0; o >>= 1) mx = fmaxf(mx, __shfl_xor_sync(0xffffffffu, mx, o));
    if ((tid & 31) == 0) red[tid >> 5] = mx;
    __syncthreads();
    if (tid == 0) {
        float m = red[0];
        #pragma unroll
        for (int w = 1; w < 8; w++) m = fmaxf(m, red[w]);
        red[0] = m;
    }
    __syncthreads();
    mx = red[0];
    __syncthreads();

    float sum = 0.f;
    #pragma unroll
    for (int l = 0; l < 4; l++) { vals[l] = expf(vals[l] - mx); sum += vals[l]; }
    #pragma unroll
    for (int o = 16; o > 0; o >>= 1) sum += __shfl_xor_sync(0xffffffffu, sum, o);
    if ((tid & 31) == 0) red[tid >> 5] = sum;
    __syncthreads();
    if (tid == 0) {
        float s = 0.f;
        #pragma unroll
        for (int w = 0; w < 8; w++) s += red[w];
        red[0] = s;
    }
    __syncthreads();
    float rinv = 1.0f / red[0];
    #pragma unroll
    for (int l = 0; l < 4; l++) {
        int j = tid + l * 256;
        attn[base + (size_t)i * T + j] = vals[l] * rinv;
    }
}

// ---------------------------------------------------------------------------
// Context (tensor core): ctx[b,i,h,d] = sum_j attn[bh,i,j] * v[b,j,h,d]
// Block tile 128i x 64d, 256 threads (8 warps: 4m x 2n), K step 32 over T.
// ---------------------------------------------------------------------------
__global__ __launch_bounds__(256) void context_tc(
    const float* __restrict__ attn, const float* __restrict__ v,
    float* __restrict__ ctx)
{
    __shared__ float As[128][33];   // attn [i][j]
    __shared__ float Bs[32][65];    // v [j][d]
    int bh = blockIdx.y;
    int b = bh >> 3, h = bh & 7;
    int bm = blockIdx.x * 128;
    int tid = threadIdx.x;
    int warp = tid >> 5, lane = tid & 31;
    int gid = lane >> 2, tig = lane & 3;
    int wm = warp >> 1, wn = warp & 1;
    size_t abase = (size_t)bh * T * T;

    float acc[2][4][4] = {};

    for (int k0 = 0; k0 < T; k0 += 32) {
        #pragma unroll
        for (int l = 0; l < 4; l++) {
            int idx = tid + l * 256;
            int row = idx >> 3, c4 = (idx & 7) * 4;
            float4 a = *(const float4*)&attn[abase + (size_t)(bm + row) * T + k0 + c4];
            As[row][c4 + 0] = f2tf32(a.x);
            As[row][c4 + 1] = f2tf32(a.y);
            As[row][c4 + 2] = f2tf32(a.z);
            As[row][c4 + 3] = f2tf32(a.w);
        }
        #pragma unroll
        for (int l = 0; l < 2; l++) {
            int idx = tid + l * 256;
            int row = idx >> 4, c4 = (idx & 15) * 4;
            float4 vv = *(const float4*)&v[(size_t)((b * T + k0 + row) * H + h) * DK + c4];
            Bs[row][c4 + 0] = f2tf32(vv.x);
            Bs[row][c4 + 1] = f2tf32(vv.y);
            Bs[row][c4 + 2] = f2tf32(vv.z);
            Bs[row][c4 + 3] = f2tf32(vv.w);
        }
        __syncthreads();

        #pragma unroll
        for (int k8 = 0; k8 < 4; k8++) {
            int kb = k8 * 8;
            float af[2][4], bf[4][2];
            #pragma unroll
            for (int mt = 0; mt < 2; mt++) {
                int r = wm * 32 + mt * 16 + gid;
                af[mt][0] = As[r][kb + tig];
                af[mt][1] = As[r + 8][kb + tig];
                af[mt][2] = As[r][kb + tig + 4];
                af[mt][3] = As[r + 8][kb + tig + 4];
            }
            #pragma unroll
            for (int nt = 0; nt < 4; nt++) {
                int cidx = wn * 32 + nt * 8 + gid;
                bf[nt][0] = Bs[kb + tig][cidx];
                bf[nt][1] = Bs[kb + tig + 4][cidx];
            }
            #pragma unroll
            for (int mt = 0; mt < 2; mt++)
                #pragma unroll
                for (int nt = 0; nt < 4; nt++)
                    mma_tf32(acc[mt][nt], af[mt], bf[nt]);
        }
        __syncthreads();
    }

    #pragma unroll
    for (int mt = 0; mt < 2; mt++) {
        int r0 = bm + wm * 32 + mt * 16 + gid;
        #pragma unroll
        for (int nt = 0; nt < 4; nt++) {
            int c0 = wn * 32 + nt * 8 + 2 * tig;
            ctx[(size_t)((b * T + r0) * H + h) * DK + c0]           = acc[mt][nt][0];
            ctx[(size_t)((b * T + r0) * H + h) * DK + c0 + 1]       = acc[mt][nt][1];
            ctx[(size_t)((b * T + r0 + 8) * H + h) * DK + c0]       = acc[mt][nt][2];
            ctx[(size_t)((b * T + r0 + 8) * H + h) * DK + c0 + 1]   = acc[mt][nt][3];
        }
    }
}

// ---------------------------------------------------------------------------
extern "C" void kernel_launch(void* const* d_in, const int* in_sizes, int n_in,
                              void* d_out, int out_size)
{
    const float* query = (const float*)d_in[0];
    const float* key   = (const float*)d_in[1];
    const float* value = (const float*)d_in[2];
    const float* pos   = (const float*)d_in[3];
    const float* Wq = (const float*)d_in[4];
    const float* bq = (const float*)d_in[5];
    const float* Wk = (const float*)d_in[6];
    const float* bk = (const float*)d_in[7];
    const float* Wv = (const float*)d_in[8];
    const float* bv = (const float*)d_in[9];
    const float* Wp = (const float*)d_in[10];
    const float* ub = (const float*)d_in[11];
    const float* vb = (const float*)d_in[12];
    const float* Wo = (const float*)d_in[13];
    const float* bo = (const float*)d_in[14];
    float* out = (float*)d_out;

    float *q, *k, *v, *p, *cs, *ps, *ctx;
    cudaGetSymbolAddress((void**)&q,   g_q);
    cudaGetSymbolAddress((void**)&k,   g_k);
    cudaGetSymbolAddress((void**)&v,   g_v);
    cudaGetSymbolAddress((void**)&p,   g_p);
    cudaGetSymbolAddress((void**)&cs,  g_cs);
    cudaGetSymbolAddress((void**)&ps,  g_ps);
    cudaGetSymbolAddress((void**)&ctx, g_ctx);

    dim3 gproj(D / 64, BT / 128);           // (8, 64)
    sgemm_bias_tc<<<gproj, 256>>>(query, Wq, bq, q, BT, D, D);
    sgemm_bias_tc<<<gproj, 256>>>(key,   Wk, bk, k, BT, D, D);
    sgemm_bias_tc<<<gproj, 256>>>(value, Wv, bv, v, BT, D, D);
    sgemm_bias_tc<<<gproj, 256>>>(pos,   Wp, nullptr, p, BT, D, D);

    dim3 gsc(T / 64, T / 64, B * H);        // (16, 16, 64)
    score_tc<<<gsc, 128>>>(q, k, ub, cs);
    score_tc<<<gsc, 128>>>(q, p, vb, ps);

    dim3 gsm(T, B * H);                     // (1024, 64)
    softmax_shift_kernel<<<gsm, 256>>>(cs, ps, cs);

    dim3 gctx(T / 128, B * H);              // (8, 64)
    context_tc<<<gctx, 256>>>(cs, v, ctx);

    sgemm_bias_tc<<<gproj, 256>>>(ctx, Wo, bo, out, BT, D, D);
}

// round 3
// speedup vs baseline: 2.2517x; 1.8398x over previous
#include <cuda_runtime.h>

#define B 8
#define T 1024
#define D 512
#define H 8
#define DK 64
#define BT (B*T)   // 8192

// Scratch (static device globals — no runtime allocation)
__device__ float g_q[BT * D];
__device__ float g_k[BT * D];
__device__ float g_v[BT * D];
__device__ float g_p[BT * D];
__device__ float g_cs[(size_t)B * H * T * T];
__device__ float g_ps[(size_t)B * H * T * T];
__device__ float g_ctx[BT * D];

__device__ __forceinline__ float f2tf32(float f) {
    unsigned u;
    asm("cvt.rna.tf32.f32 %0, %1;" : "=r"(u) : "f"(f));
    return __uint_as_float(u);
}

// mma.sync m16n8k8 tf32 row.col
__device__ __forceinline__ void mma_tf32(float* c, const float* a, const float* b) {
    asm volatile(
        "mma.sync.aligned.m16n8k8.row.col.f32.tf32.tf32.f32 "
        "{%0,%1,%2,%3}, {%4,%5,%6,%7}, {%8,%9}, {%0,%1,%2,%3};"
        : "+f"(c[0]), "+f"(c[1]), "+f"(c[2]), "+f"(c[3])
        : "r"(__float_as_uint(a[0])), "r"(__float_as_uint(a[1])),
          "r"(__float_as_uint(a[2])), "r"(__float_as_uint(a[3])),
          "r"(__float_as_uint(b[0])), "r"(__float_as_uint(b[1])));
}

// ---------------------------------------------------------------------------
// GEMM: C[M,N] = A[M,K] @ W[K,N] (+bias). Block 128x128, 256 thr (8 warps 2x4),
// warp tile 64x32, K-step 16, double-buffered, register-staged prefetch.
// ---------------------------------------------------------------------------
__global__ __launch_bounds__(256) void sgemm_bias_tc(
    const float* __restrict__ A, const float* __restrict__ W,
    const float* __restrict__ bias, float* __restrict__ C,
    int M, int N, int K)
{
    __shared__ float As[2][128][20];   // stride 20: banks 4g+t distinct
    __shared__ float Bs[2][16][136];   // stride 136: banks 8t+g distinct
    int tid = threadIdx.x, warp = tid >> 5, lane = tid & 31;
    int gid = lane >> 2, tig = lane & 3;
    int wm = warp & 1, wn = warp >> 1;
    int bm = blockIdx.y * 128, bn = blockIdx.x * 128;
    int arow = tid >> 2, ac4 = (tid & 3) * 4;
    int brow = tid >> 5, bc4 = (tid & 31) * 4;

    const float* Ap0 = A + (size_t)(bm + arow) * K + ac4;
    const float* Ap1 = A + (size_t)(bm + arow + 64) * K + ac4;
    const float* Wp0 = W + (size_t)brow * N + bn + bc4;
    const float* Wp1 = W + (size_t)(brow + 8) * N + bn + bc4;

    float4 sa0 = *(const float4*)Ap0;
    float4 sa1 = *(const float4*)Ap1;
    float4 sb0 = *(const float4*)Wp0;
    float4 sb1 = *(const float4*)Wp1;

    float acc[4][4][4] = {};
    int nsteps = K / 16;
    for (int s = 0; s < nsteps; s++) {
        int buf = s & 1;
        As[buf][arow][ac4+0] = f2tf32(sa0.x); As[buf][arow][ac4+1] = f2tf32(sa0.y);
        As[buf][arow][ac4+2] = f2tf32(sa0.z); As[buf][arow][ac4+3] = f2tf32(sa0.w);
        As[buf][arow+64][ac4+0] = f2tf32(sa1.x); As[buf][arow+64][ac4+1] = f2tf32(sa1.y);
        As[buf][arow+64][ac4+2] = f2tf32(sa1.z); As[buf][arow+64][ac4+3] = f2tf32(sa1.w);
        Bs[buf][brow][bc4+0] = f2tf32(sb0.x); Bs[buf][brow][bc4+1] = f2tf32(sb0.y);
        Bs[buf][brow][bc4+2] = f2tf32(sb0.z); Bs[buf][brow][bc4+3] = f2tf32(sb0.w);
        Bs[buf][brow+8][bc4+0] = f2tf32(sb1.x); Bs[buf][brow+8][bc4+1] = f2tf32(sb1.y);
        Bs[buf][brow+8][bc4+2] = f2tf32(sb1.z); Bs[buf][brow+8][bc4+3] = f2tf32(sb1.w);
        __syncthreads();

        if (s + 1 < nsteps) {
            int k0 = (s + 1) * 16;
            sa0 = *(const float4*)(Ap0 + k0);
            sa1 = *(const float4*)(Ap1 + k0);
            sb0 = *(const float4*)(Wp0 + (size_t)k0 * N);
            sb1 = *(const float4*)(Wp1 + (size_t)k0 * N);
        }

        #pragma unroll
        for (int k8 = 0; k8 < 2; k8++) {
            int kb = k8 * 8;
            float af[4][4], bf[4][2];
            #pragma unroll
            for (int mt = 0; mt < 4; mt++) {
                int r = wm * 64 + mt * 16 + gid;
                af[mt][0] = As[buf][r][kb + tig];
                af[mt][1] = As[buf][r + 8][kb + tig];
                af[mt][2] = As[buf][r][kb + tig + 4];
                af[mt][3] = As[buf][r + 8][kb + tig + 4];
            }
            #pragma unroll
            for (int nt = 0; nt < 4; nt++) {
                int c = wn * 32 + nt * 8 + gid;
                bf[nt][0] = Bs[buf][kb + tig][c];
                bf[nt][1] = Bs[buf][kb + tig + 4][c];
            }
            #pragma unroll
            for (int mt = 0; mt < 4; mt++)
                #pragma unroll
                for (int nt = 0; nt < 4; nt++)
                    mma_tf32(acc[mt][nt], af[mt], bf[nt]);
        }
        __syncthreads();
    }

    #pragma unroll
    for (int mt = 0; mt < 4; mt++) {
        int r0 = bm + wm * 64 + mt * 16 + gid;
        #pragma unroll
        for (int nt = 0; nt < 4; nt++) {
            int c0 = bn + wn * 32 + nt * 8 + 2 * tig;
            float b0 = bias ? bias[c0] : 0.f;
            float b1 = bias ? bias[c0 + 1] : 0.f;
            C[(size_t)r0 * N + c0]           = acc[mt][nt][0] + b0;
            C[(size_t)r0 * N + c0 + 1]       = acc[mt][nt][1] + b1;
            C[(size_t)(r0 + 8) * N + c0]     = acc[mt][nt][2] + b0;
            C[(size_t)(r0 + 8) * N + c0 + 1] = acc[mt][nt][3] + b1;
        }
    }
}

// ---------------------------------------------------------------------------
// Fused scores: one block computes 128x128 tiles of BOTH
//   cs[bh,i,j] = scale * (q+u)·k   and   ps[bh,i,j] = scale * (q+v)·p
// Q tile loaded once (two biased tf32 copies), K then P share one smem tile.
// Dynamic smem: 3 * 128 * 68 floats.
// ---------------------------------------------------------------------------
#define QSTR 68
__device__ __forceinline__ void score_mma_store(
    const float* __restrict__ Q, const float* __restrict__ KP,
    float* __restrict__ out, size_t obase, int bi, int bj,
    int wm, int wn, int gid, int tig)
{
    float acc[4][4][4] = {};
    #pragma unroll
    for (int k8 = 0; k8 < 8; k8++) {
        int kb = k8 * 8;
        float af[4][4], bf[4][2];
        #pragma unroll
        for (int mt = 0; mt < 4; mt++) {
            int r = wm * 64 + mt * 16 + gid;
            af[mt][0] = Q[r * QSTR + kb + tig];
            af[mt][1] = Q[(r + 8) * QSTR + kb + tig];
            af[mt][2] = Q[r * QSTR + kb + tig + 4];
            af[mt][3] = Q[(r + 8) * QSTR + kb + tig + 4];
        }
        #pragma unroll
        for (int nt = 0; nt < 4; nt++) {
            int c = wn * 32 + nt * 8 + gid;
            bf[nt][0] = KP[c * QSTR + kb + tig];
            bf[nt][1] = KP[c * QSTR + kb + tig + 4];
        }
        #pragma unroll
        for (int mt = 0; mt < 4; mt++)
            #pragma unroll
            for (int nt = 0; nt < 4; nt++)
                mma_tf32(acc[mt][nt], af[mt], bf[nt]);
    }
    const float scale = 0.04419417382415922f;   // 1/sqrt(512)
    #pragma unroll
    for (int mt = 0; mt < 4; mt++) {
        int r0 = bi + wm * 64 + mt * 16 + gid;
        #pragma unroll
        for (int nt = 0; nt < 4; nt++) {
            int c0 = bj + wn * 32 + nt * 8 + 2 * tig;
            out[obase + (size_t)r0 * T + c0]           = acc[mt][nt][0] * scale;
            out[obase + (size_t)r0 * T + c0 + 1]       = acc[mt][nt][1] * scale;
            out[obase + (size_t)(r0 + 8) * T + c0]     = acc[mt][nt][2] * scale;
            out[obase + (size_t)(r0 + 8) * T + c0 + 1] = acc[mt][nt][3] * scale;
        }
    }
}

__global__ __launch_bounds__(256) void score_fused(
    const float* __restrict__ q, const float* __restrict__ k,
    const float* __restrict__ p, const float* __restrict__ ub,
    const float* __restrict__ vb, float* __restrict__ cs, float* __restrict__ ps)
{
    extern __shared__ float sm[];
    float* Qu = sm;
    float* Qv = sm + 128 * QSTR;
    float* KP = sm + 2 * 128 * QSTR;

    int bh = blockIdx.z, b = bh >> 3, h = bh & 7;
    int bi = blockIdx.y * 128, bj = blockIdx.x * 128;
    int tid = threadIdx.x, warp = tid >> 5, lane = tid & 31;
    int gid = lane >> 2, tig = lane & 3;
    int wm = warp & 1, wn = warp >> 1;
    size_t obase = (size_t)bh * T * T;

    // Load Q tile with both biases (128x64 -> 2048 float4, 8/thread)
    #pragma unroll
    for (int l = 0; l < 8; l++) {
        int idx = tid + l * 256;
        int row = idx >> 4, c4 = (idx & 15) * 4;
        float4 vq = *(const float4*)&q[(size_t)((b * T + bi + row) * H + h) * DK + c4];
        float4 uu = *(const float4*)&ub[h * DK + c4];
        float4 vv = *(const float4*)&vb[h * DK + c4];
        Qu[row * QSTR + c4 + 0] = f2tf32(vq.x + uu.x);
        Qu[row * QSTR + c4 + 1] = f2tf32(vq.y + uu.y);
        Qu[row * QSTR + c4 + 2] = f2tf32(vq.z + uu.z);
        Qu[row * QSTR + c4 + 3] = f2tf32(vq.w + uu.w);
        Qv[row * QSTR + c4 + 0] = f2tf32(vq.x + vv.x);
        Qv[row * QSTR + c4 + 1] = f2tf32(vq.y + vv.y);
        Qv[row * QSTR + c4 + 2] = f2tf32(vq.z + vv.z);
        Qv[row * QSTR + c4 + 3] = f2tf32(vq.w + vv.w);
        float4 vk = *(const float4*)&k[(size_t)((b * T + bj + row) * H + h) * DK + c4];
        KP[row * QSTR + c4 + 0] = f2tf32(vk.x);
        KP[row * QSTR + c4 + 1] = f2tf32(vk.y);
        KP[row * QSTR + c4 + 2] = f2tf32(vk.z);
        KP[row * QSTR + c4 + 3] = f2tf32(vk.w);
    }
    __syncthreads();

    score_mma_store(Qu, KP, cs, obase, bi, bj, wm, wn, gid, tig);
    __syncthreads();   // all warps done reading K before overwrite

    #pragma unroll
    for (int l = 0; l < 8; l++) {
        int idx = tid + l * 256;
        int row = idx >> 4, c4 = (idx & 15) * 4;
        float4 vp = *(const float4*)&p[(size_t)((b * T + bj + row) * H + h) * DK + c4];
        KP[row * QSTR + c4 + 0] = f2tf32(vp.x);
        KP[row * QSTR + c4 + 1] = f2tf32(vp.y);
        KP[row * QSTR + c4 + 2] = f2tf32(vp.z);
        KP[row * QSTR + c4 + 3] = f2tf32(vp.w);
    }
    __syncthreads();

    score_mma_store(Qv, KP, ps, obase, bi, bj, wm, wn, gid, tig);
}

// ---------------------------------------------------------------------------
// Fused rel-shift + softmax (scale already folded into scores).
// ---------------------------------------------------------------------------
__global__ __launch_bounds__(256) void softmax_shift_kernel(
    const float* __restrict__ cs, const float* __restrict__ ps,
    float* __restrict__ attn)
{
    int i  = blockIdx.x;
    int bh = blockIdx.y;
    int tid = threadIdx.x;
    size_t base = (size_t)bh * T * T;

    float vals[4];
    float mx = -3.4e38f;
    #pragma unroll
    for (int l = 0; l < 4; l++) {
        int j = tid + l * 256;
        int flat = (i + 1) * T + j;
        int ii = flat / (T + 1);
        int c  = flat - ii * (T + 1);
        float pv = (c == 0) ? 0.0f : ps[base + (size_t)ii * T + (c - 1)];
        float s = cs[base + (size_t)i * T + j] + pv;
        vals[l] = s;
        mx = fmaxf(mx, s);
    }

    __shared__ float red[8];
    #pragma unroll
    for (int o = 16; o > 0; o >>= 1) mx = fmaxf(mx, __shfl_xor_sync(0xffffffffu, mx, o));
    if ((tid & 31) == 0) red[tid >> 5] = mx;
    __syncthreads();
    if (tid == 0) {
        float m = red[0];
        #pragma unroll
        for (int w = 1; w < 8; w++) m = fmaxf(m, red[w]);
        red[0] = m;
    }
    __syncthreads();
    mx = red[0];
    __syncthreads();

    float sum = 0.f;
    #pragma unroll
    for (int l = 0; l < 4; l++) { vals[l] = expf(vals[l] - mx); sum += vals[l]; }
    #pragma unroll
    for (int o = 16; o > 0; o >>= 1) sum += __shfl_xor_sync(0xffffffffu, sum, o);
    if ((tid & 31) == 0) red[tid >> 5] = sum;
    __syncthreads();
    if (tid == 0) {
        float s = 0.f;
        #pragma unroll
        for (int w = 0; w < 8; w++) s += red[w];
        red[0] = s;
    }
    __syncthreads();
    float rinv = 1.0f / red[0];
    #pragma unroll
    for (int l = 0; l < 4; l++) {
        int j = tid + l * 256;
        attn[base + (size_t)i * T + j] = vals[l] * rinv;
    }
}

// ---------------------------------------------------------------------------
// Context: ctx[b,i,h,d] = sum_j attn[bh,i,j] * v[b,j,h,d]
// Block 128i x 64d, 256 thr (8 warps 4x2), warp 32x32, K-step 16, double-buf.
// ---------------------------------------------------------------------------
__global__ __launch_bounds__(256) void context_tc(
    const float* __restrict__ attn, const float* __restrict__ v,
    float* __restrict__ ctx)
{
    __shared__ float As[2][128][20];
    __shared__ float Bs[2][16][72];
    int bh = blockIdx.y, b = bh >> 3, h = bh & 7;
    int bm = blockIdx.x * 128;
    int tid = threadIdx.x, warp = tid >> 5, lane = tid & 31;
    int gid = lane >> 2, tig = lane & 3;
    int wm = warp >> 1, wn = warp & 1;
    int arow = tid >> 2, ac4 = (tid & 3) * 4;
    int brow = tid >> 4, bc4 = (tid & 15) * 4;
    size_t abase = (size_t)bh * T * T;

    const float* Ap0 = attn + abase + (size_t)(bm + arow) * T + ac4;
    const float* Ap1 = attn + abase + (size_t)(bm + arow + 64) * T + ac4;
    const float* Vp  = v + (size_t)((b * T + brow) * H + h) * DK + bc4;

    float4 sa0 = *(const float4*)Ap0;
    float4 sa1 = *(const float4*)Ap1;
    float4 sb  = *(const float4*)Vp;

    float acc[2][4][4] = {};
    for (int s = 0; s < T / 16; s++) {
        int buf = s & 1;
        As[buf][arow][ac4+0] = f2tf32(sa0.x); As[buf][arow][ac4+1] = f2tf32(sa0.y);
        As[buf][arow][ac4+2] = f2tf32(sa0.z); As[buf][arow][ac4+3] = f2tf32(sa0.w);
        As[buf][arow+64][ac4+0] = f2tf32(sa1.x); As[buf][arow+64][ac4+1] = f2tf32(sa1.y);
        As[buf][arow+64][ac4+2] = f2tf32(sa1.z); As[buf][arow+64][ac4+3] = f2tf32(sa1.w);
        Bs[buf][brow][bc4+0] = f2tf32(sb.x); Bs[buf][brow][bc4+1] = f2tf32(sb.y);
        Bs[buf][brow][bc4+2] = f2tf32(sb.z); Bs[buf][brow][bc4+3] = f2tf32(sb.w);
        __syncthreads();

        if (s + 1 < T / 16) {
            int k0 = (s + 1) * 16;
            sa0 = *(const float4*)(Ap0 + k0);
            sa1 = *(const float4*)(Ap1 + k0);
            sb  = *(const float4*)(Vp + (size_t)k0 * H * DK);
        }

        #pragma unroll
        for (int k8 = 0; k8 < 2; k8++) {
            int kb = k8 * 8;
            float af[2][4], bf[4][2];
            #pragma unroll
            for (int mt = 0; mt < 2; mt++) {
                int r = wm * 32 + mt * 16 + gid;
                af[mt][0] = As[buf][r][kb + tig];
                af[mt][1] = As[buf][r + 8][kb + tig];
                af[mt][2] = As[buf][r][kb + tig + 4];
                af[mt][3] = As[buf][r + 8][kb + tig + 4];
            }
            #pragma unroll
            for (int nt = 0; nt < 4; nt++) {
                int c = wn * 32 + nt * 8 + gid;
                bf[nt][0] = Bs[buf][kb + tig][c];
                bf[nt][1] = Bs[buf][kb + tig + 4][c];
            }
            #pragma unroll
            for (int mt = 0; mt < 2; mt++)
                #pragma unroll
                for (int nt = 0; nt < 4; nt++)
                    mma_tf32(acc[mt][nt], af[mt], bf[nt]);
        }
        __syncthreads();
    }

    #pragma unroll
    for (int mt = 0; mt < 2; mt++) {
        int r0 = bm + wm * 32 + mt * 16 + gid;
        #pragma unroll
        for (int nt = 0; nt < 4; nt++) {
            int c0 = wn * 32 + nt * 8 + 2 * tig;
            ctx[(size_t)((b * T + r0) * H + h) * DK + c0]         = acc[mt][nt][0];
            ctx[(size_t)((b * T + r0) * H + h) * DK + c0 + 1]     = acc[mt][nt][1];
            ctx[(size_t)((b * T + r0 + 8) * H + h) * DK + c0]     = acc[mt][nt][2];
            ctx[(size_t)((b * T + r0 + 8) * H + h) * DK + c0 + 1] = acc[mt][nt][3];
        }
    }
}

// ---------------------------------------------------------------------------
extern "C" void kernel_launch(void* const* d_in, const int* in_sizes, int n_in,
                              void* d_out, int out_size)
{
    const float* query = (const float*)d_in[0];
    const float* key   = (const float*)d_in[1];
    const float* value = (const float*)d_in[2];
    const float* pos   = (const float*)d_in[3];
    const float* Wq = (const float*)d_in[4];
    const float* bq = (const float*)d_in[5];
    const float* Wk = (const float*)d_in[6];
    const float* bk = (const float*)d_in[7];
    const float* Wv = (const float*)d_in[8];
    const float* bv = (const float*)d_in[9];
    const float* Wp = (const float*)d_in[10];
    const float* ub = (const float*)d_in[11];
    const float* vb = (const float*)d_in[12];
    const float* Wo = (const float*)d_in[13];
    const float* bo = (const float*)d_in[14];
    float* out = (float*)d_out;

    float *q, *k, *v, *p, *cs, *ps, *ctx;
    cudaGetSymbolAddress((void**)&q,   g_q);
    cudaGetSymbolAddress((void**)&k,   g_k);
    cudaGetSymbolAddress((void**)&v,   g_v);
    cudaGetSymbolAddress((void**)&p,   g_p);
    cudaGetSymbolAddress((void**)&cs,  g_cs);
    cudaGetSymbolAddress((void**)&ps,  g_ps);
    cudaGetSymbolAddress((void**)&ctx, g_ctx);

    const int SMEM_SCORE = 3 * 128 * QSTR * 4;   // 104448 B
    cudaFuncSetAttribute(score_fused,
        cudaFuncAttributeMaxDynamicSharedMemorySize, SMEM_SCORE);

    dim3 gproj(D / 128, BT / 128);          // (4, 64)
    sgemm_bias_tc<<<gproj, 256>>>(query, Wq, bq, q, BT, D, D);
    sgemm_bias_tc<<<gproj, 256>>>(key,   Wk, bk, k, BT, D, D);
    sgemm_bias_tc<<<gproj, 256>>>(value, Wv, bv, v, BT, D, D);
    sgemm_bias_tc<<<gproj, 256>>>(pos,   Wp, nullptr, p, BT, D, D);

    dim3 gsc(T / 128, T / 128, B * H);      // (8, 8, 64)
    score_fused<<<gsc, 256, SMEM_SCORE>>>(q, k, p, ub, vb, cs, ps);

    dim3 gsm(T, B * H);                     // (1024, 64)
    softmax_shift_kernel<<<gsm, 256>>>(cs, ps, cs);

    dim3 gctx(T / 128, B * H);              // (8, 64)
    context_tc<<<gctx, 256>>>(cs, v, ctx);

    sgemm_bias_tc<<<gproj, 256>>>(ctx, Wo, bo, out, BT, D, D);
}

// round 4
// speedup vs baseline: 2.3470x; 1.0423x over previous
#include <cuda_runtime.h>

#define B 8
#define T 1024
#define D 512
#define H 8
#define DK 64
#define BT (B*T)   // 8192

__device__ float g_q[BT * D];
__device__ float g_k[BT * D];
__device__ float g_v[BT * D];
__device__ float g_p[BT * D];
__device__ float g_cs[(size_t)B * H * T * T];
__device__ float g_ps[(size_t)B * H * T * T];
__device__ float g_ctx[BT * D];

// mma.sync m16n8k8 tf32 row.col  (raw fp32 bits; HW truncates mantissa)
__device__ __forceinline__ void mma_tf32(float* c, const float* a, const float* b) {
    asm volatile(
        "mma.sync.aligned.m16n8k8.row.col.f32.tf32.tf32.f32 "
        "{%0,%1,%2,%3}, {%4,%5,%6,%7}, {%8,%9}, {%0,%1,%2,%3};"
        : "+f"(c[0]), "+f"(c[1]), "+f"(c[2]), "+f"(c[3])
        : "r"(__float_as_uint(a[0])), "r"(__float_as_uint(a[1])),
          "r"(__float_as_uint(a[2])), "r"(__float_as_uint(a[3])),
          "r"(__float_as_uint(b[0])), "r"(__float_as_uint(b[1])));
}

__device__ __forceinline__ void cp16(float* dst, const float* src) {
    unsigned d = (unsigned)__cvta_generic_to_shared(dst);
    asm volatile("cp.async.ca.shared.global [%0], [%1], 16;" :: "r"(d), "l"(src));
}
__device__ __forceinline__ void cp_commit() { asm volatile("cp.async.commit_group;"); }
__device__ __forceinline__ void cp_wait1()  { asm volatile("cp.async.wait_group 1;"); }
__device__ __forceinline__ void cp_wait0()  { asm volatile("cp.async.wait_group 0;"); }

// ---------------------------------------------------------------------------
// GEMM: C[M,N] = A[M,K] @ W[K,N] (+bias). Block 128x128, 256 thr (8 warps 2x4),
// warp 64x32, K-step 16, 3-stage cp.async pipeline. Dynamic smem.
// ---------------------------------------------------------------------------
__global__ __launch_bounds__(256, 2) void sgemm_bias_tc(
    const float* __restrict__ A, const float* __restrict__ W,
    const float* __restrict__ bias, float* __restrict__ C,
    int M, int N, int K)
{
    extern __shared__ float sm[];
    float (*As)[128][20] = reinterpret_cast<float(*)[128][20]>(sm);
    float (*Bs)[16][136] = reinterpret_cast<float(*)[16][136]>(sm + 3 * 128 * 20);

    int tid = threadIdx.x, warp = tid >> 5, lane = tid & 31;
    int gid = lane >> 2, tig = lane & 3;
    int wm = warp & 1, wn = warp >> 1;
    int bm = blockIdx.y * 128, bn = blockIdx.x * 128;
    int ar = tid >> 2, ac = (tid & 3) * 4;
    int br = tid >> 5, bc = (tid & 31) * 4;

    const float* Abase = A + (size_t)(bm + ar) * K + ac;
    const float* Wbase = W + (size_t)br * N + bn + bc;
    int nsteps = K / 16;

    #pragma unroll
    for (int s = 0; s < 2; s++) {
        int k0 = s * 16;
        cp16(&As[s][ar][ac],      Abase + k0);
        cp16(&As[s][ar + 64][ac], Abase + (size_t)64 * K + k0);
        cp16(&Bs[s][br][bc],      Wbase + (size_t)k0 * N);
        cp16(&Bs[s][br + 8][bc],  Wbase + (size_t)(k0 + 8) * N);
        cp_commit();
    }

    float acc[4][4][4] = {};
    for (int s = 0; s < nsteps; s++) {
        cp_wait1();
        __syncthreads();
        int st = s % 3;
        if (s + 2 < nsteps) {
            int k0 = (s + 2) * 16, st2 = (s + 2) % 3;
            cp16(&As[st2][ar][ac],      Abase + k0);
            cp16(&As[st2][ar + 64][ac], Abase + (size_t)64 * K + k0);
            cp16(&Bs[st2][br][bc],      Wbase + (size_t)k0 * N);
            cp16(&Bs[st2][br + 8][bc],  Wbase + (size_t)(k0 + 8) * N);
        }
        cp_commit();

        #pragma unroll
        for (int k8 = 0; k8 < 2; k8++) {
            int kb = k8 * 8;
            float af[4][4], bf[4][2];
            #pragma unroll
            for (int mt = 0; mt < 4; mt++) {
                int r = wm * 64 + mt * 16 + gid;
                af[mt][0] = As[st][r][kb + tig];
                af[mt][1] = As[st][r + 8][kb + tig];
                af[mt][2] = As[st][r][kb + tig + 4];
                af[mt][3] = As[st][r + 8][kb + tig + 4];
            }
            #pragma unroll
            for (int nt = 0; nt < 4; nt++) {
                int c = wn * 32 + nt * 8 + gid;
                bf[nt][0] = Bs[st][kb + tig][c];
                bf[nt][1] = Bs[st][kb + tig + 4][c];
            }
            #pragma unroll
            for (int mt = 0; mt < 4; mt++)
                #pragma unroll
                for (int nt = 0; nt < 4; nt++)
                    mma_tf32(acc[mt][nt], af[mt], bf[nt]);
        }
    }

    #pragma unroll
    for (int mt = 0; mt < 4; mt++) {
        int r0 = bm + wm * 64 + mt * 16 + gid;
        #pragma unroll
        for (int nt = 0; nt < 4; nt++) {
            int c0 = bn + wn * 32 + nt * 8 + 2 * tig;
            float b0 = bias ? bias[c0] : 0.f;
            float b1 = bias ? bias[c0 + 1] : 0.f;
            C[(size_t)r0 * N + c0]           = acc[mt][nt][0] + b0;
            C[(size_t)r0 * N + c0 + 1]       = acc[mt][nt][1] + b1;
            C[(size_t)(r0 + 8) * N + c0]     = acc[mt][nt][2] + b0;
            C[(size_t)(r0 + 8) * N + c0 + 1] = acc[mt][nt][3] + b1;
        }
    }
}

// ---------------------------------------------------------------------------
// Fused scores: 128x128 tiles of cs = scale*(q+u)·k and ps = scale*(q+v)·p.
// ---------------------------------------------------------------------------
#define QSTR 68
__device__ __forceinline__ void score_mma_store(
    const float* __restrict__ Q, const float* __restrict__ KP,
    float* __restrict__ out, size_t obase, int bi, int bj,
    int wm, int wn, int gid, int tig)
{
    float acc[4][4][4] = {};
    #pragma unroll
    for (int k8 = 0; k8 < 8; k8++) {
        int kb = k8 * 8;
        float af[4][4], bf[4][2];
        #pragma unroll
        for (int mt = 0; mt < 4; mt++) {
            int r = wm * 64 + mt * 16 + gid;
            af[mt][0] = Q[r * QSTR + kb + tig];
            af[mt][1] = Q[(r + 8) * QSTR + kb + tig];
            af[mt][2] = Q[r * QSTR + kb + tig + 4];
            af[mt][3] = Q[(r + 8) * QSTR + kb + tig + 4];
        }
        #pragma unroll
        for (int nt = 0; nt < 4; nt++) {
            int c = wn * 32 + nt * 8 + gid;
            bf[nt][0] = KP[c * QSTR + kb + tig];
            bf[nt][1] = KP[c * QSTR + kb + tig + 4];
        }
        #pragma unroll
        for (int mt = 0; mt < 4; mt++)
            #pragma unroll
            for (int nt = 0; nt < 4; nt++)
                mma_tf32(acc[mt][nt], af[mt], bf[nt]);
    }
    const float scale = 0.04419417382415922f;   // 1/sqrt(512)
    #pragma unroll
    for (int mt = 0; mt < 4; mt++) {
        int r0 = bi + wm * 64 + mt * 16 + gid;
        #pragma unroll
        for (int nt = 0; nt < 4; nt++) {
            int c0 = bj + wn * 32 + nt * 8 + 2 * tig;
            out[obase + (size_t)r0 * T + c0]           = acc[mt][nt][0] * scale;
            out[obase + (size_t)r0 * T + c0 + 1]       = acc[mt][nt][1] * scale;
            out[obase + (size_t)(r0 + 8) * T + c0]     = acc[mt][nt][2] * scale;
            out[obase + (size_t)(r0 + 8) * T + c0 + 1] = acc[mt][nt][3] * scale;
        }
    }
}

__global__ __launch_bounds__(256) void score_fused(
    const float* __restrict__ q, const float* __restrict__ k,
    const float* __restrict__ p, const float* __restrict__ ub,
    const float* __restrict__ vb, float* __restrict__ cs, float* __restrict__ ps)
{
    extern __shared__ float sm[];
    float* Qu = sm;
    float* Qv = sm + 128 * QSTR;
    float* KP = sm + 2 * 128 * QSTR;

    int bh = blockIdx.z, b = bh >> 3, h = bh & 7;
    int bi = blockIdx.y * 128, bj = blockIdx.x * 128;
    int tid = threadIdx.x, warp = tid >> 5, lane = tid & 31;
    int gid = lane >> 2, tig = lane & 3;
    int wm = warp & 1, wn = warp >> 1;
    size_t obase = (size_t)bh * T * T;

    // async K tile (overlaps with Q processing)
    #pragma unroll
    for (int l = 0; l < 8; l++) {
        int idx = tid + l * 256;
        int row = idx >> 4, c4 = (idx & 15) * 4;
        cp16(&KP[row * QSTR + c4], &k[(size_t)((b * T + bj + row) * H + h) * DK + c4]);
    }
    cp_commit();

    // Q tile with both biases
    #pragma unroll
    for (int l = 0; l < 8; l++) {
        int idx = tid + l * 256;
        int row = idx >> 4, c4 = (idx & 15) * 4;
        float4 vq = *(const float4*)&q[(size_t)((b * T + bi + row) * H + h) * DK + c4];
        float4 uu = *(const float4*)&ub[h * DK + c4];
        float4 vv = *(const float4*)&vb[h * DK + c4];
        Qu[row * QSTR + c4 + 0] = vq.x + uu.x;
        Qu[row * QSTR + c4 + 1] = vq.y + uu.y;
        Qu[row * QSTR + c4 + 2] = vq.z + uu.z;
        Qu[row * QSTR + c4 + 3] = vq.w + uu.w;
        Qv[row * QSTR + c4 + 0] = vq.x + vv.x;
        Qv[row * QSTR + c4 + 1] = vq.y + vv.y;
        Qv[row * QSTR + c4 + 2] = vq.z + vv.z;
        Qv[row * QSTR + c4 + 3] = vq.w + vv.w;
    }
    cp_wait0();
    __syncthreads();

    score_mma_store(Qu, KP, cs, obase, bi, bj, wm, wn, gid, tig);
    __syncthreads();

    #pragma unroll
    for (int l = 0; l < 8; l++) {
        int idx = tid + l * 256;
        int row = idx >> 4, c4 = (idx & 15) * 4;
        cp16(&KP[row * QSTR + c4], &p[(size_t)((b * T + bj + row) * H + h) * DK + c4]);
    }
    cp_commit();
    cp_wait0();
    __syncthreads();

    score_mma_store(Qv, KP, ps, obase, bi, bj, wm, wn, gid, tig);
}

// ---------------------------------------------------------------------------
// Fused rel-shift + softmax (scale folded into scores).
// ---------------------------------------------------------------------------
__global__ __launch_bounds__(256) void softmax_shift_kernel(
    const float* __restrict__ cs, const float* __restrict__ ps,
    float* __restrict__ attn)
{
    int i  = blockIdx.x;
    int bh = blockIdx.y;
    int tid = threadIdx.x;
    size_t base = (size_t)bh * T * T;

    float vals[4];
    float mx = -3.4e38f;
    #pragma unroll
    for (int l = 0; l < 4; l++) {
        int j = tid + l * 256;
        int flat = (i + 1) * T + j;
        int ii = flat / (T + 1);
        int c  = flat - ii * (T + 1);
        float pv = (c == 0) ? 0.0f : ps[base + (size_t)ii * T + (c - 1)];
        float s = cs[base + (size_t)i * T + j] + pv;
        vals[l] = s;
        mx = fmaxf(mx, s);
    }

    __shared__ float red[8];
    #pragma unroll
    for (int o = 16; o > 0; o >>= 1) mx = fmaxf(mx, __shfl_xor_sync(0xffffffffu, mx, o));
    if ((tid & 31) == 0) red[tid >> 5] = mx;
    __syncthreads();
    if (tid == 0) {
        float m = red[0];
        #pragma unroll
        for (int w = 1; w < 8; w++) m = fmaxf(m, red[w]);
        red[0] = m;
    }
    __syncthreads();
    mx = red[0];
    __syncthreads();

    float sum = 0.f;
    #pragma unroll
    for (int l = 0; l < 4; l++) { vals[l] = expf(vals[l] - mx); sum += vals[l]; }
    #pragma unroll
    for (int o = 16; o > 0; o >>= 1) sum += __shfl_xor_sync(0xffffffffu, sum, o);
    if ((tid & 31) == 0) red[tid >> 5] = sum;
    __syncthreads();
    if (tid == 0) {
        float s = 0.f;
        #pragma unroll
        for (int w = 0; w < 8; w++) s += red[w];
        red[0] = s;
    }
    __syncthreads();
    float rinv = 1.0f / red[0];
    #pragma unroll
    for (int l = 0; l < 4; l++) {
        int j = tid + l * 256;
        attn[base + (size_t)i * T + j] = vals[l] * rinv;
    }
}

// ---------------------------------------------------------------------------
// Context: ctx[b,i,h,d] = sum_j attn[bh,i,j] * v[b,j,h,d]
// Block 128i x 64d, 256 thr (8 warps 4x2), K-step 16, 3-stage cp.async.
// ---------------------------------------------------------------------------
__global__ __launch_bounds__(256, 2) void context_tc(
    const float* __restrict__ attn, const float* __restrict__ v,
    float* __restrict__ ctx)
{
    __shared__ float As[3][128][20];
    __shared__ float Bs[3][16][72];
    int bh = blockIdx.y, b = bh >> 3, h = bh & 7;
    int bm = blockIdx.x * 128;
    int tid = threadIdx.x, warp = tid >> 5, lane = tid & 31;
    int gid = lane >> 2, tig = lane & 3;
    int wm = warp >> 1, wn = warp & 1;
    int ar = tid >> 2, ac = (tid & 3) * 4;
    int br = tid >> 4, bc = (tid & 15) * 4;
    size_t abase = (size_t)bh * T * T;

    const float* Abase = attn + abase + (size_t)(bm + ar) * T + ac;
    const float* Vbase = v + (size_t)((b * T + br) * H + h) * DK + bc;
    const int nsteps = T / 16;

    #pragma unroll
    for (int s = 0; s < 2; s++) {
        int k0 = s * 16;
        cp16(&As[s][ar][ac],      Abase + k0);
        cp16(&As[s][ar + 64][ac], Abase + (size_t)64 * T + k0);
        cp16(&Bs[s][br][bc],      Vbase + (size_t)k0 * H * DK);
        cp_commit();
    }

    float acc[2][4][4] = {};
    for (int s = 0; s < nsteps; s++) {
        cp_wait1();
        __syncthreads();
        int st = s % 3;
        if (s + 2 < nsteps) {
            int k0 = (s + 2) * 16, st2 = (s + 2) % 3;
            cp16(&As[st2][ar][ac],      Abase + k0);
            cp16(&As[st2][ar + 64][ac], Abase + (size_t)64 * T + k0);
            cp16(&Bs[st2][br][bc],      Vbase + (size_t)k0 * H * DK);
        }
        cp_commit();

        #pragma unroll
        for (int k8 = 0; k8 < 2; k8++) {
            int kb = k8 * 8;
            float af[2][4], bf[4][2];
            #pragma unroll
            for (int mt = 0; mt < 2; mt++) {
                int r = wm * 32 + mt * 16 + gid;
                af[mt][0] = As[st][r][kb + tig];
                af[mt][1] = As[st][r + 8][kb + tig];
                af[mt][2] = As[st][r][kb + tig + 4];
                af[mt][3] = As[st][r + 8][kb + tig + 4];
            }
            #pragma unroll
            for (int nt = 0; nt < 4; nt++) {
                int c = wn * 32 + nt * 8 + gid;
                bf[nt][0] = Bs[st][kb + tig][c];
                bf[nt][1] = Bs[st][kb + tig + 4][c];
            }
            #pragma unroll
            for (int mt = 0; mt < 2; mt++)
                #pragma unroll
                for (int nt = 0; nt < 4; nt++)
                    mma_tf32(acc[mt][nt], af[mt], bf[nt]);
        }
    }

    #pragma unroll
    for (int mt = 0; mt < 2; mt++) {
        int r0 = bm + wm * 32 + mt * 16 + gid;
        #pragma unroll
        for (int nt = 0; nt < 4; nt++) {
            int c0 = wn * 32 + nt * 8 + 2 * tig;
            ctx[(size_t)((b * T + r0) * H + h) * DK + c0]         = acc[mt][nt][0];
            ctx[(size_t)((b * T + r0) * H + h) * DK + c0 + 1]     = acc[mt][nt][1];
            ctx[(size_t)((b * T + r0 + 8) * H + h) * DK + c0]     = acc[mt][nt][2];
            ctx[(size_t)((b * T + r0 + 8) * H + h) * DK + c0 + 1] = acc[mt][nt][3];
        }
    }
}

// ---------------------------------------------------------------------------
extern "C" void kernel_launch(void* const* d_in, const int* in_sizes, int n_in,
                              void* d_out, int out_size)
{
    const float* query = (const float*)d_in[0];
    const float* key   = (const float*)d_in[1];
    const float* value = (const float*)d_in[2];
    const float* pos   = (const float*)d_in[3];
    const float* Wq = (const float*)d_in[4];
    const float* bq = (const float*)d_in[5];
    const float* Wk = (const float*)d_in[6];
    const float* bk = (const float*)d_in[7];
    const float* Wv = (const float*)d_in[8];
    const float* bv = (const float*)d_in[9];
    const float* Wp = (const float*)d_in[10];
    const float* ub = (const float*)d_in[11];
    const float* vb = (const float*)d_in[12];
    const float* Wo = (const float*)d_in[13];
    const float* bo = (const float*)d_in[14];
    float* out = (float*)d_out;

    float *q, *k, *v, *p, *cs, *ps, *ctx;
    cudaGetSymbolAddress((void**)&q,   g_q);
    cudaGetSymbolAddress((void**)&k,   g_k);
    cudaGetSymbolAddress((void**)&v,   g_v);
    cudaGetSymbolAddress((void**)&p,   g_p);
    cudaGetSymbolAddress((void**)&cs,  g_cs);
    cudaGetSymbolAddress((void**)&ps,  g_ps);
    cudaGetSymbolAddress((void**)&ctx, g_ctx);

    const int SMEM_GEMM  = (3 * 128 * 20 + 3 * 16 * 136) * 4;   // 56832 B
    const int SMEM_SCORE = 3 * 128 * QSTR * 4;                  // 104448 B
    cudaFuncSetAttribute(sgemm_bias_tc,
        cudaFuncAttributeMaxDynamicSharedMemorySize, SMEM_GEMM);
    cudaFuncSetAttribute(score_fused,
        cudaFuncAttributeMaxDynamicSharedMemorySize, SMEM_SCORE);

    dim3 gproj(D / 128, BT / 128);          // (4, 64)
    sgemm_bias_tc<<<gproj, 256, SMEM_GEMM>>>(query, Wq, bq, q, BT, D, D);
    sgemm_bias_tc<<<gproj, 256, SMEM_GEMM>>>(key,   Wk, bk, k, BT, D, D);
    sgemm_bias_tc<<<gproj, 256, SMEM_GEMM>>>(value, Wv, bv, v, BT, D, D);
    sgemm_bias_tc<<<gproj, 256, SMEM_GEMM>>>(pos,   Wp, nullptr, p, BT, D, D);

    dim3 gsc(T / 128, T / 128, B * H);      // (8, 8, 64)
    score_fused<<<gsc, 256, SMEM_SCORE>>>(q, k, p, ub, vb, cs, ps);

    dim3 gsm(T, B * H);                     // (1024, 64)
    softmax_shift_kernel<<<gsm, 256>>>(cs, ps, cs);

    dim3 gctx(T / 128, B * H);              // (8, 64)
    context_tc<<<gctx, 256>>>(cs, v, ctx);

    sgemm_bias_tc<<<gproj, 256, SMEM_GEMM>>>(ctx, Wo, bo, out, BT, D, D);
}